// round 1
// baseline (speedup 1.0000x reference)
#include <cuda_runtime.h>
#include <cstdint>
#include <cstddef>

#define BM 128
#define BN 128
#define BK 64
#define PITCH 80            // smem row pitch in bytes (64 data + 16 pad -> conflict-free ldmatrix)
#define NTHREADS 256
#define ABUF (BM * PITCH)
#define BBUF (BN * PITCH)

// ---- scratch (device globals; no allocations allowed) ----
__device__ unsigned g_amax[2];                      // [0]=amax(x) bits, [1]=amax(w) bits
__device__ int8_t   g_qx[(size_t)8192 * 4096];      // quantized x  (max shape)
__device__ int8_t   g_qw[(size_t)4096 * 4096];      // quantized w  (max shape)

__global__ void init_kernel() { g_amax[0] = 0u; g_amax[1] = 0u; }

// ---- pass 1: max|t| reduction (bit-max on nonnegative floats == float max) ----
__global__ void absmax_kernel(const float4* __restrict__ in, long n4, int which) {
    unsigned m = 0u;
    for (long i = (long)blockIdx.x * blockDim.x + threadIdx.x; i < n4;
         i += (long)gridDim.x * blockDim.x) {
        float4 v = in[i];
        float a = fmaxf(fmaxf(fabsf(v.x), fabsf(v.y)), fmaxf(fabsf(v.z), fabsf(v.w)));
        m = max(m, __float_as_uint(a));
    }
#pragma unroll
    for (int o = 16; o; o >>= 1) m = max(m, __shfl_xor_sync(0xffffffffu, m, o));
    __shared__ unsigned sm[8];
    if ((threadIdx.x & 31) == 0) sm[threadIdx.x >> 5] = m;
    __syncthreads();
    if (threadIdx.x < 8) {
        unsigned v = sm[threadIdx.x];
#pragma unroll
        for (int o = 4; o; o >>= 1) v = max(v, __shfl_xor_sync(0xffu, v, o));
        if (threadIdx.x == 0) atomicMax(&g_amax[which], v);
    }
}

// ---- pass 2: symmetric int8 quantization, exact match of jnp round-half-even + clip ----
__global__ void quant_kernel(const float4* __restrict__ in, long n4, int which) {
    long i = (long)blockIdx.x * blockDim.x + threadIdx.x;
    if (i >= n4) return;
    float s = 127.0f / __uint_as_float(g_amax[which]);
    float4 v = in[i];
    char4 o;
    o.x = (char)(int)fminf(127.0f, fmaxf(-127.0f, rintf(v.x * s)));
    o.y = (char)(int)fminf(127.0f, fmaxf(-127.0f, rintf(v.y * s)));
    o.z = (char)(int)fminf(127.0f, fmaxf(-127.0f, rintf(v.z * s)));
    o.w = (char)(int)fminf(127.0f, fmaxf(-127.0f, rintf(v.w * s)));
    char4* q4 = which ? (char4*)g_qw : (char4*)g_qx;
    q4[i] = o;
}

// ---- helpers ----
__device__ __forceinline__ void cp16(uint32_t smem, const void* gmem) {
    asm volatile("cp.async.cg.shared.global [%0], [%1], 16;\n" ::"r"(smem), "l"(gmem));
}
__device__ __forceinline__ void ldsm4(uint32_t& r0, uint32_t& r1, uint32_t& r2, uint32_t& r3,
                                      uint32_t addr) {
    asm volatile("ldmatrix.sync.aligned.m8n8.x4.shared.b16 {%0,%1,%2,%3}, [%4];"
                 : "=r"(r0), "=r"(r1), "=r"(r2), "=r"(r3)
                 : "r"(addr));
}
__device__ __forceinline__ void mma_s8(int* c, const uint32_t* a, const uint32_t* b) {
    asm volatile(
        "mma.sync.aligned.m16n8k32.row.col.s32.s8.s8.s32 "
        "{%0,%1,%2,%3}, {%4,%5,%6,%7}, {%8,%9}, {%0,%1,%2,%3};"
        : "+r"(c[0]), "+r"(c[1]), "+r"(c[2]), "+r"(c[3])
        : "r"(a[0]), "r"(a[1]), "r"(a[2]), "r"(a[3]), "r"(b[0]), "r"(b[1]));
}

// ---- pass 3: int8 GEMM, C[N,M] = qx[N,K] * qw[M,K]^T, dequant + bias epilogue ----
__global__ void __launch_bounds__(NTHREADS)
gemm_kernel(const float* __restrict__ bias, float* __restrict__ out, int N, int M, int K) {
    __shared__ int8_t sA[2][ABUF];
    __shared__ int8_t sB[2][BBUF];

    const int tid  = threadIdx.x;
    const int lane = tid & 31;
    const int warp = tid >> 5;
    const int warp_m = (warp >> 2) * 64;   // 2 warps along M-of-tile (N dim rows)
    const int warp_n = (warp & 3) * 32;    // 4 warps along N-of-tile (M dim cols)
    const int n0 = blockIdx.y * BM;        // rows of x  (N dimension)
    const int m0 = blockIdx.x * BN;        // rows of w  (M dimension)

    const uint32_t sA_base = (uint32_t)__cvta_generic_to_shared(&sA[0][0]);
    const uint32_t sB_base = (uint32_t)__cvta_generic_to_shared(&sB[0][0]);

    int acc[4][4][4] = {};

    const int NIT = K / BK;

    // stage loader: 256 threads x 2 chunks of 16B for A and for B
    auto load_stage = [&](int kt, int buf) {
        const int k0 = kt * BK;
#pragma unroll
        for (int i = 0; i < 2; i++) {
            int ch  = tid + i * NTHREADS;
            int row = ch >> 2;
            int col = (ch & 3) * 16;
            cp16(sA_base + buf * ABUF + row * PITCH + col,
                 g_qx + (size_t)(n0 + row) * K + k0 + col);
            cp16(sB_base + buf * BBUF + row * PITCH + col,
                 g_qw + (size_t)(m0 + row) * K + k0 + col);
        }
    };

    load_stage(0, 0);
    asm volatile("cp.async.commit_group;\n" ::);

    int buf = 0;
    for (int kt = 0; kt < NIT; kt++) {
        asm volatile("cp.async.wait_group 0;\n" ::);
        __syncthreads();
        if (kt + 1 < NIT) {
            load_stage(kt + 1, buf ^ 1);
            asm volatile("cp.async.commit_group;\n" ::);
        }
        // compute on current buffer: 2 k-steps of 32
#pragma unroll
        for (int ks = 0; ks < 2; ks++) {
            uint32_t a[4][4];
            uint32_t b[4][2];
#pragma unroll
            for (int mf = 0; mf < 4; mf++) {
                uint32_t addr = sA_base + buf * ABUF +
                                (warp_m + mf * 16 + (lane & 15)) * PITCH +
                                ks * 32 + ((lane & 16) ? 16 : 0);
                ldsm4(a[mf][0], a[mf][1], a[mf][2], a[mf][3], addr);
            }
#pragma unroll
            for (int np = 0; np < 2; np++) {
                uint32_t addr = sB_base + buf * BBUF +
                                (warp_n + np * 16 + ((lane & 16) ? 8 : 0) + (lane & 7)) * PITCH +
                                ks * 32 + ((lane & 8) ? 16 : 0);
                ldsm4(b[2 * np][0], b[2 * np][1], b[2 * np + 1][0], b[2 * np + 1][1], addr);
            }
#pragma unroll
            for (int mf = 0; mf < 4; mf++)
#pragma unroll
                for (int nf = 0; nf < 4; nf++) mma_s8(acc[mf][nf], a[mf], b[nf]);
        }
        __syncthreads();
        buf ^= 1;
    }

    // epilogue: dequant + bias
    const float ax = __uint_as_float(g_amax[0]);
    const float aw = __uint_as_float(g_amax[1]);
    const float dq = (ax * aw) / (127.0f * 127.0f);

#pragma unroll
    for (int mf = 0; mf < 4; mf++) {
#pragma unroll
        for (int nf = 0; nf < 4; nf++) {
            int row = n0 + warp_m + mf * 16 + (lane >> 2);
            int col = m0 + warp_n + nf * 8 + (lane & 3) * 2;
            float b0 = bias[col];
            float b1 = bias[col + 1];
            float2 v0 = make_float2((float)acc[mf][nf][0] * dq + b0,
                                    (float)acc[mf][nf][1] * dq + b1);
            float2 v1 = make_float2((float)acc[mf][nf][2] * dq + b0,
                                    (float)acc[mf][nf][3] * dq + b1);
            *(float2*)&out[(size_t)row * M + col]       = v0;
            *(float2*)&out[(size_t)(row + 8) * M + col] = v1;
        }
    }
}

extern "C" void kernel_launch(void* const* d_in, const int* in_sizes, int n_in,
                              void* d_out, int out_size) {
    const float* x    = (const float*)d_in[0];
    const float* w    = (const float*)d_in[1];
    const float* bias = (const float*)d_in[2];
    float* out = (float*)d_out;

    const long M = in_sizes[2];
    const long K = (long)in_sizes[1] / M;
    const long N = (long)in_sizes[0] / K;

    init_kernel<<<1, 1>>>();

    const long nx4 = N * K / 4;
    const long nw4 = M * K / 4;
    absmax_kernel<<<2048, 256>>>((const float4*)x, nx4, 0);
    absmax_kernel<<<2048, 256>>>((const float4*)w, nw4, 1);
    quant_kernel<<<(unsigned)((nx4 + 255) / 256), 256>>>((const float4*)x, nx4, 0);
    quant_kernel<<<(unsigned)((nw4 + 255) / 256), 256>>>((const float4*)w, nw4, 1);

    dim3 grid((unsigned)(M / BN), (unsigned)(N / BM));
    gemm_kernel<<<grid, NTHREADS>>>(bias, out, (int)N, (int)M, (int)K);
}